// round 13
// baseline (speedup 1.0000x reference)
#include <cuda_runtime.h>
#include <cuda_bf16.h>
#include <cstdint>

#define N_NODES 50000
#define N_EDGES 800000
#define HID 128
#define NUM_GRAPHS 500
#define N_LAYERS 3
#define LN_EPS 1e-5f

#define SCAN_BLK 256
#define SCAN_NB  ((N_NODES + SCAN_BLK - 1) / SCAN_BLK)   // 196
#define GEMM_BLOCKS ((N_NODES + 127) / 128)              // 391
#define FILL_BLOCKS ((N_EDGES / 2 + 255) / 256)          // 1563

// ---------------- scratch (device globals) ----------------------------------
__device__ float g_deg[N_NODES];                      // dinv
__device__ int   g_indeg[N_NODES];
__device__ int   g_off[N_NODES + 1];
__device__ int   g_cur[N_NODES];
__device__ int   g_bsum[SCAN_NB];
__device__ int   g_bbase[SCAN_NB];
__device__ int2  g_epack[N_EDGES];                    // {src, bits(weight)}
__device__ float g_h[(size_t)N_NODES * HID];
__device__ float g_hw[(size_t)N_NODES * HID];
// per mat: hi 8192 u32 (n*64 + kpair), lo 8192 u32
__device__ uint32_t g_wbf[4 * 16384];

// ---------------- bf16 hi/lo pack helper -------------------------------------
__device__ __forceinline__ void pack_hilo(float x0, float x1,
                                          uint32_t& hp, uint32_t& lp) {
    unsigned short h0 = __bfloat16_as_ushort(__float2bfloat16(x0));
    unsigned short h1 = __bfloat16_as_ushort(__float2bfloat16(x1));
    float r0 = x0 - __uint_as_float((uint32_t)h0 << 16);
    float r1 = x1 - __uint_as_float((uint32_t)h1 << 16);
    unsigned short l0 = __bfloat16_as_ushort(__float2bfloat16(r0));
    unsigned short l1 = __bfloat16_as_ushort(__float2bfloat16(r1));
    hp = (uint32_t)h0 | ((uint32_t)h1 << 16);
    lp = (uint32_t)l0 | ((uint32_t)l1 << 16);
}

#define MMA_BF16(d, a, bv0, bv1)                                                \
    asm volatile("mma.sync.aligned.m16n8k16.row.col.f32.bf16.bf16.f32 "         \
        "{%0,%1,%2,%3}, {%4,%5,%6,%7}, {%8,%9}, {%0,%1,%2,%3};"                 \
        : "+f"((d)[0]), "+f"((d)[1]), "+f"((d)[2]), "+f"((d)[3])                \
        : "r"((a)[0]), "r"((a)[1]), "r"((a)[2]), "r"((a)[3]),                   \
          "r"(bv0), "r"(bv1));

// ---------------- merged init (indeg zero) + weight convert -------------------
__global__ __launch_bounds__(256) void k_initwconv(const float* __restrict__ W_in,
                                                   const float* __restrict__ Wc) {
    if (blockIdx.x < 4) {
        int mat = blockIdx.x;             // 0 = W_in, 1..3 = Wc[l]
        int n = threadIdx.x;
        if (n >= 128) return;
        const float* W = (mat == 0) ? W_in : Wc + (size_t)(mat - 1) * 16384;
        uint32_t* hi = g_wbf + (size_t)mat * 16384 + n * 64;
        uint32_t* lo = hi + 8192;
        const float2* wr = reinterpret_cast<const float2*>(W + (size_t)n * 128);
#pragma unroll
        for (int p = 0; p < 64; ++p) {
            float2 v = wr[p];
            pack_hilo(v.x, v.y, hi[p], lo[p]);
        }
    } else {
        int i = (blockIdx.x - 4) * 256 + threadIdx.x;
        if (i < N_NODES) g_indeg[i] = 0;
    }
}

// ---------------- in-degree histogram (4 edges/thread, int4 loads) ------------
__global__ void k_hist(const int* __restrict__ dst) {
    int i = blockIdx.x * blockDim.x + threadIdx.x;
    if (i * 4 >= N_EDGES) return;
    int4 d = reinterpret_cast<const int4*>(dst)[i];
    atomicAdd(&g_indeg[d.x], 1);
    atomicAdd(&g_indeg[d.y], 1);
    atomicAdd(&g_indeg[d.z], 1);
    atomicAdd(&g_indeg[d.w], 1);
}

// ---------------- 3-phase full-chip scan --------------------------------------
__global__ __launch_bounds__(SCAN_BLK) void k_scanA() {
    __shared__ int ws[8];
    int t = threadIdx.x, lane = t & 31, wid = t >> 5;
    int i = blockIdx.x * SCAN_BLK + t;
    int v = (i < N_NODES) ? g_indeg[i] : 0;
    int s = v;
#pragma unroll
    for (int o = 16; o > 0; o >>= 1) s += __shfl_xor_sync(0xffffffffu, s, o);
    if (lane == 0) ws[wid] = s;
    __syncthreads();
    if (t < 8) {
        int x = ws[t];
#pragma unroll
        for (int o = 4; o > 0; o >>= 1) x += __shfl_xor_sync(0xffu, x, o);
        if (t == 0) g_bsum[blockIdx.x] = x;
    }
}

__global__ __launch_bounds__(256) void k_scanB() {
    __shared__ int ws[8];
    int t = threadIdx.x, lane = t & 31, wid = t >> 5;
    int v = (t < SCAN_NB) ? g_bsum[t] : 0;
    int x = v;
#pragma unroll
    for (int o = 1; o < 32; o <<= 1) {
        int y = __shfl_up_sync(0xffffffffu, x, o);
        if (lane >= o) x += y;
    }
    if (lane == 31) ws[wid] = x;
    __syncthreads();
    if (wid == 0 && lane < 8) {
        int s = ws[lane];
#pragma unroll
        for (int o = 1; o < 8; o <<= 1) {
            int y = __shfl_up_sync(0xffu, s, o);
            if (lane >= o) s += y;
        }
        ws[lane] = s;
    }
    __syncthreads();
    int incl = x + (wid ? ws[wid - 1] : 0);
    if (t < SCAN_NB) g_bbase[t] = incl - v;
    if (t == 255) g_off[N_NODES] = incl;
}

__global__ __launch_bounds__(SCAN_BLK) void k_scanC() {
    __shared__ int ws[8];
    int t = threadIdx.x, lane = t & 31, wid = t >> 5;
    int i = blockIdx.x * SCAN_BLK + t;
    int v = (i < N_NODES) ? g_indeg[i] : 0;
    int x = v;
#pragma unroll
    for (int o = 1; o < 32; o <<= 1) {
        int y = __shfl_up_sync(0xffffffffu, x, o);
        if (lane >= o) x += y;
    }
    if (lane == 31) ws[wid] = x;
    __syncthreads();
    if (wid == 0 && lane < 8) {
        int s = ws[lane];
#pragma unroll
        for (int o = 1; o < 8; o <<= 1) {
            int y = __shfl_up_sync(0xffu, s, o);
            if (lane >= o) s += y;
        }
        ws[lane] = s;
    }
    __syncthreads();
    if (i < N_NODES) {
        int off = g_bbase[blockIdx.x] + (wid ? ws[wid - 1] : 0) + (x - v);
        g_off[i] = off;
        g_cur[i] = off;
        g_deg[i] = rsqrtf((float)v + 1.f);
    }
}

// ---------------- tensor-core GEMM (+ optional fused CSR fill blocks) ---------
// Blocks [0, GEMM_BLOCKS): C[M,128] = A[M,128] @ W^T (+bias), bf16x3 mma.sync.
// Blocks [GEMM_BLOCKS, ...): CSR bucket fill (mode-0 launch only) — independent
// work co-scheduled to hide fill latency under the GEMM.
#define GSTR 36
#define GEMM_SMEM (4 * 128 * GSTR * 4)    // 73728 B

__global__ __launch_bounds__(256) void k_gemmmma(
    const float* A_ext, int mat, const float* __restrict__ bias, int M, int mode,
    const int* __restrict__ src, const int* __restrict__ dst)
{
    // ---- fused fill path (extra blocks of the mode-0 launch) ----
    if (blockIdx.x >= GEMM_BLOCKS) {
        int i = (blockIdx.x - GEMM_BLOCKS) * 256 + threadIdx.x;
        int e = i * 2;
        if (e >= N_EDGES) return;
        int2 s2 = reinterpret_cast<const int2*>(src)[i];
        int2 d2 = reinterpret_cast<const int2*>(dst)[i];
        int slot0 = atomicAdd(&g_cur[d2.x], 1);
        int slot1 = atomicAdd(&g_cur[d2.y], 1);
        g_epack[slot0] = make_int2(s2.x, __float_as_int(g_deg[s2.x] * g_deg[d2.x]));
        g_epack[slot1] = make_int2(s2.y, __float_as_int(g_deg[s2.y] * g_deg[d2.y]));
        return;
    }

    extern __shared__ uint32_t sm[];
    uint32_t* AsHi = sm;
    uint32_t* AsLo = sm + 128 * GSTR;
    uint32_t* WsHi = sm + 2 * 128 * GSTR;
    uint32_t* WsLo = sm + 3 * 128 * GSTR;

    const float* A = (mode == 0) ? A_ext : g_h;
    float* C = (mode == 0) ? g_h : g_hw;

    int t = threadIdx.x;
    int lane = t & 31, w = t >> 5;
    int wm = w >> 1;
    int wn = w & 1;
    int lr = lane >> 2, lq = lane & 3;
    int row0 = blockIdx.x * 128;

    int cr = t >> 1;
    int ch = t & 1;

    float acc[2][8][4];
#pragma unroll
    for (int i = 0; i < 2; ++i)
#pragma unroll
        for (int j = 0; j < 8; ++j)
#pragma unroll
            for (int q = 0; q < 4; ++q) acc[i][j][q] = 0.f;

    const uint32_t* gwH = g_wbf + (size_t)mat * 16384;

#pragma unroll 1
    for (int c = 0; c < 2; ++c) {
        {
            int gr = row0 + cr;
            const float4* arow = (gr < M)
                ? reinterpret_cast<const float4*>(A + (size_t)gr * 128 + c * 64 + ch * 32)
                : (const float4*)0;
            uint4* dh = reinterpret_cast<uint4*>(AsHi + cr * GSTR + ch * 16);
            uint4* dl = reinterpret_cast<uint4*>(AsLo + cr * GSTR + ch * 16);
#pragma unroll
            for (int i = 0; i < 4; ++i) {
                float4 v0 = arow ? arow[2 * i] : make_float4(0.f, 0.f, 0.f, 0.f);
                float4 v1 = arow ? arow[2 * i + 1] : make_float4(0.f, 0.f, 0.f, 0.f);
                uint32_t hp0, lp0, hp1, lp1, hp2, lp2, hp3, lp3;
                pack_hilo(v0.x, v0.y, hp0, lp0);
                pack_hilo(v0.z, v0.w, hp1, lp1);
                pack_hilo(v1.x, v1.y, hp2, lp2);
                pack_hilo(v1.z, v1.w, hp3, lp3);
                dh[i] = make_uint4(hp0, hp1, hp2, hp3);
                dl[i] = make_uint4(lp0, lp1, lp2, lp3);
            }
            const uint4* sH = reinterpret_cast<const uint4*>(
                gwH + cr * 64 + c * 32 + ch * 16);
            const uint4* sL = reinterpret_cast<const uint4*>(
                gwH + 8192 + cr * 64 + c * 32 + ch * 16);
            uint4* wh = reinterpret_cast<uint4*>(WsHi + cr * GSTR + ch * 16);
            uint4* wl = reinterpret_cast<uint4*>(WsLo + cr * GSTR + ch * 16);
#pragma unroll
            for (int i = 0; i < 4; ++i) { wh[i] = sH[i]; wl[i] = sL[i]; }
        }
        __syncthreads();

#pragma unroll
        for (int s = 0; s < 4; ++s) {
            int w0 = s * 8 + lq;
            uint32_t ah[2][4], al[2][4];
#pragma unroll
            for (int tm = 0; tm < 2; ++tm) {
                int ra = (wm * 32 + tm * 16 + lr) * GSTR + w0;
                ah[tm][0] = AsHi[ra];
                ah[tm][1] = AsHi[ra + 8 * GSTR];
                ah[tm][2] = AsHi[ra + 4];
                ah[tm][3] = AsHi[ra + 8 * GSTR + 4];
                al[tm][0] = AsLo[ra];
                al[tm][1] = AsLo[ra + 8 * GSTR];
                al[tm][2] = AsLo[ra + 4];
                al[tm][3] = AsLo[ra + 8 * GSTR + 4];
            }
#pragma unroll
            for (int j = 0; j < 8; ++j) {
                int rb = (wn * 64 + j * 8 + lr) * GSTR + w0;
                uint32_t bh0 = WsHi[rb], bh1 = WsHi[rb + 4];
                uint32_t bl0 = WsLo[rb], bl1 = WsLo[rb + 4];
#pragma unroll
                for (int tm = 0; tm < 2; ++tm) {
                    MMA_BF16(acc[tm][j], ah[tm], bh0, bh1);
                    MMA_BF16(acc[tm][j], ah[tm], bl0, bl1);
                    MMA_BF16(acc[tm][j], al[tm], bh0, bh1);
                }
            }
        }
        __syncthreads();
    }

#pragma unroll
    for (int tm = 0; tm < 2; ++tm) {
        int row = row0 + wm * 32 + tm * 16 + lr;
#pragma unroll
        for (int j = 0; j < 8; ++j) {
            int col = wn * 64 + j * 8 + lq * 2;
            float bx = 0.f, by = 0.f;
            if (bias) {
                float2 bv = *reinterpret_cast<const float2*>(bias + col);
                bx = bv.x; by = bv.y;
            }
            if (row < M) {
                float2 v = make_float2(acc[tm][j][0] + bx, acc[tm][j][1] + by);
                *reinterpret_cast<float2*>(C + (size_t)row * 128 + col) = v;
            }
            if (row + 8 < M) {
                float2 v = make_float2(acc[tm][j][2] + bx, acc[tm][j][3] + by);
                *reinterpret_cast<float2*>(C + (size_t)(row + 8) * 128 + col) = v;
            }
        }
    }
}

// ---------------- fused gather + self-loop + LN + ReLU + residual ------------
// warp per dst node, 8 edges in flight (round-10 proven form — frozen).
#define EDGE4(E)                                                                \
    {                                                                           \
        int2 p0 = g_epack[E], p1 = g_epack[(E) + 1];                            \
        int2 p2 = g_epack[(E) + 2], p3 = g_epack[(E) + 3];                      \
        float4 v0 = reinterpret_cast<const float4*>(g_hw + (size_t)p0.x * HID)[lane]; \
        float4 v1 = reinterpret_cast<const float4*>(g_hw + (size_t)p1.x * HID)[lane]; \
        float4 v2 = reinterpret_cast<const float4*>(g_hw + (size_t)p2.x * HID)[lane]; \
        float4 v3 = reinterpret_cast<const float4*>(g_hw + (size_t)p3.x * HID)[lane]; \
        float w0 = __int_as_float(p0.y), w1 = __int_as_float(p1.y);             \
        float w2 = __int_as_float(p2.y), w3 = __int_as_float(p3.y);             \
        acc.x += w0 * v0.x + w1 * v1.x + w2 * v2.x + w3 * v3.x;                 \
        acc.y += w0 * v0.y + w1 * v1.y + w2 * v2.y + w3 * v3.y;                 \
        acc.z += w0 * v0.z + w1 * v1.z + w2 * v2.z + w3 * v3.z;                 \
        acc.w += w0 * v0.w + w1 * v1.w + w2 * v2.w + w3 * v3.w;                 \
    }

__global__ __launch_bounds__(256) void k_gatherln(
    const float* __restrict__ bc,
    const float* __restrict__ gamma, const float* __restrict__ beta)
{
    int node = (blockIdx.x * blockDim.x + threadIdx.x) >> 5;
    int lane = threadIdx.x & 31;
    if (node >= N_NODES) return;

    int e0 = g_off[node], e1 = g_off[node + 1];
    float dv = g_deg[node];
    float sn = dv * dv;

    float4 hv  = reinterpret_cast<const float4*>(g_hw + (size_t)node * HID)[lane];
    float4 bcv = reinterpret_cast<const float4*>(bc)[lane];
    float4 acc = make_float4(hv.x * sn + bcv.x, hv.y * sn + bcv.y,
                             hv.z * sn + bcv.z, hv.w * sn + bcv.w);

    int e = e0;
#pragma unroll 1
    for (; e + 8 <= e1; e += 8) {
        EDGE4(e)
        EDGE4(e + 4)
    }
    if (e + 4 <= e1) { EDGE4(e) e += 4; }
#pragma unroll 1
    for (; e < e1; ++e) {
        int2 p = g_epack[e];
        float w = __int_as_float(p.y);
        float4 v = reinterpret_cast<const float4*>(g_hw + (size_t)p.x * HID)[lane];
        acc.x += w * v.x; acc.y += w * v.y;
        acc.z += w * v.z; acc.w += w * v.w;
    }

    float s = acc.x + acc.y + acc.z + acc.w;
#pragma unroll
    for (int o = 16; o > 0; o >>= 1) s += __shfl_xor_sync(0xffffffffu, s, o);
    float mu = s * (1.f / 128.f);
    float dx = acc.x - mu, dy = acc.y - mu, dz = acc.z - mu, dw = acc.w - mu;
    float q = dx * dx + dy * dy + dz * dz + dw * dw;
#pragma unroll
    for (int o = 16; o > 0; o >>= 1) q += __shfl_xor_sync(0xffffffffu, q, o);
    float rs = rsqrtf(q * (1.f / 128.f) + LN_EPS);

    float4 gm = reinterpret_cast<const float4*>(gamma)[lane];
    float4 bt = reinterpret_cast<const float4*>(beta)[lane];
    float4 r  = reinterpret_cast<const float4*>(g_h + (size_t)node * HID)[lane];
    float4 o;
    o.x = fmaxf(dx * rs * gm.x + bt.x, 0.f) + r.x;
    o.y = fmaxf(dy * rs * gm.y + bt.y, 0.f) + r.y;
    o.z = fmaxf(dz * rs * gm.z + bt.z, 0.f) + r.z;
    o.w = fmaxf(dw * rs * gm.w + bt.w, 0.f) + r.w;
    reinterpret_cast<float4*>(g_h + (size_t)node * HID)[lane] = o;
}

// ---------------- fused pool + MLP (block per graph, atomic-free) ------------
__global__ __launch_bounds__(128) void k_poolmlp(
    const int* __restrict__ batch,
    const float* __restrict__ W1, const float* __restrict__ b1,
    const float* __restrict__ W2, const float* __restrict__ b2,
    float* __restrict__ out)
{
    __shared__ float sp[128];
    __shared__ float part[2];
    int g = blockIdx.x, t = threadIdx.x;

    int lo = 0, hi = N_NODES;
    while (lo < hi) { int m = (lo + hi) >> 1; if (batch[m] < g) lo = m + 1; else hi = m; }
    int start = lo;
    hi = N_NODES;
    while (lo < hi) { int m = (lo + hi) >> 1; if (batch[m] < g + 1) lo = m + 1; else hi = m; }
    int end = lo;

    float acc = 0.f;
    for (int r = start; r < end; ++r) acc += g_h[(size_t)r * HID + t];
    float inv = 1.f / fmaxf((float)(end - start), 1.f);
    sp[t] = acc * inv;
    __syncthreads();

    if (t < 64) {
        float a = b1[t];
#pragma unroll 8
        for (int k = 0; k < 128; ++k) a += sp[k] * W1[t * 128 + k];
        a = fmaxf(a, 0.f);
        float v = a * W2[t];
#pragma unroll
        for (int o = 16; o > 0; o >>= 1) v += __shfl_xor_sync(0xffffffffu, v, o);
        if ((t & 31) == 0) part[t >> 5] = v;
    }
    __syncthreads();
    if (t == 0) out[g] = part[0] + part[1] + b2[0];
}

// ---------------- launch -----------------------------------------------------
extern "C" void kernel_launch(void* const* d_in, const int* in_sizes, int n_in,
                              void* d_out, int out_size) {
    const float* x     = (const float*)d_in[0];
    const int*   ei    = (const int*)  d_in[1];
    const int*   batch = (const int*)  d_in[2];
    const float* W_in  = (const float*)d_in[3];
    const float* b_in  = (const float*)d_in[4];
    const float* Wc    = (const float*)d_in[5];
    const float* bc    = (const float*)d_in[6];
    const float* gamma = (const float*)d_in[7];
    const float* beta  = (const float*)d_in[8];
    const float* W1    = (const float*)d_in[9];
    const float* b1    = (const float*)d_in[10];
    const float* W2    = (const float*)d_in[11];
    const float* b2    = (const float*)d_in[12];
    float* out = (float*)d_out;

    const int* src = ei;
    const int* dst = ei + N_EDGES;

    cudaFuncSetAttribute(k_gemmmma, cudaFuncAttributeMaxDynamicSharedMemorySize,
                         GEMM_SMEM);

    k_initwconv<<<4 + (N_NODES + 255) / 256, 256>>>(W_in, Wc);
    k_hist<<<(N_EDGES / 4 + 255) / 256, 256>>>(dst);
    k_scanA<<<SCAN_NB, SCAN_BLK>>>();
    k_scanB<<<1, 256>>>();
    k_scanC<<<SCAN_NB, SCAN_BLK>>>();

    // mode-0 GEMM with fused CSR fill blocks (independent work, co-scheduled)
    k_gemmmma<<<GEMM_BLOCKS + FILL_BLOCKS, 256, GEMM_SMEM>>>(
        x, 0, b_in, N_NODES, 0, src, dst);

    int gl_blocks = (N_NODES * 32 + 255) / 256;
    for (int l = 0; l < N_LAYERS; ++l) {
        k_gemmmma<<<GEMM_BLOCKS, 256, GEMM_SMEM>>>(
            (const float*)0, l + 1, (const float*)0, N_NODES, 1,
            (const int*)0, (const int*)0);
        k_gatherln<<<gl_blocks, 256>>>(bc + l * HID, gamma + l * HID, beta + l * HID);
    }

    k_poolmlp<<<NUM_GRAPHS, 128>>>(batch, W1, b1, W2, b2, out);
}

// round 14
// speedup vs baseline: 1.4654x; 1.4654x over previous
#include <cuda_runtime.h>
#include <cuda_bf16.h>
#include <cstdint>

#define N_NODES 50000
#define N_EDGES 800000
#define HID 128
#define NUM_GRAPHS 500
#define N_LAYERS 3
#define LN_EPS 1e-5f

#define SCAN_BLK 256
#define SCAN_NB  ((N_NODES + SCAN_BLK - 1) / SCAN_BLK)   // 196

// ---------------- scratch (device globals) ----------------------------------
__device__ float g_deg[N_NODES];                      // dinv
__device__ int   g_indeg[N_NODES];
__device__ int   g_off[N_NODES + 1];
__device__ int   g_cur[N_NODES];
__device__ int   g_bsum[SCAN_NB];
__device__ int   g_bbase[SCAN_NB];
__device__ int2  g_epack[N_EDGES];                    // {src, bits(weight)}
__device__ float g_h[(size_t)N_NODES * HID];
__device__ float g_hw[(size_t)N_NODES * HID];
// per mat: hi 8192 u32 (n*64 + kpair), lo 8192 u32
__device__ uint32_t g_wbf[4 * 16384];

// ---------------- bf16 hi/lo pack helper -------------------------------------
__device__ __forceinline__ void pack_hilo(float x0, float x1,
                                          uint32_t& hp, uint32_t& lp) {
    unsigned short h0 = __bfloat16_as_ushort(__float2bfloat16(x0));
    unsigned short h1 = __bfloat16_as_ushort(__float2bfloat16(x1));
    float r0 = x0 - __uint_as_float((uint32_t)h0 << 16);
    float r1 = x1 - __uint_as_float((uint32_t)h1 << 16);
    unsigned short l0 = __bfloat16_as_ushort(__float2bfloat16(r0));
    unsigned short l1 = __bfloat16_as_ushort(__float2bfloat16(r1));
    hp = (uint32_t)h0 | ((uint32_t)h1 << 16);
    lp = (uint32_t)l0 | ((uint32_t)l1 << 16);
}

#define MMA_BF16(d, a, bv0, bv1)                                                \
    asm volatile("mma.sync.aligned.m16n8k16.row.col.f32.bf16.bf16.f32 "         \
        "{%0,%1,%2,%3}, {%4,%5,%6,%7}, {%8,%9}, {%0,%1,%2,%3};"                 \
        : "+f"((d)[0]), "+f"((d)[1]), "+f"((d)[2]), "+f"((d)[3])                \
        : "r"((a)[0]), "r"((a)[1]), "r"((a)[2]), "r"((a)[3]),                   \
          "r"(bv0), "r"(bv1));

// ---------------- merged init (indeg zero) + weight convert -------------------
__global__ __launch_bounds__(256) void k_initwconv(const float* __restrict__ W_in,
                                                   const float* __restrict__ Wc) {
    if (blockIdx.x < 4) {
        int mat = blockIdx.x;             // 0 = W_in, 1..3 = Wc[l]
        int n = threadIdx.x;
        if (n >= 128) return;
        const float* W = (mat == 0) ? W_in : Wc + (size_t)(mat - 1) * 16384;
        uint32_t* hi = g_wbf + (size_t)mat * 16384 + n * 64;
        uint32_t* lo = hi + 8192;
        const float2* wr = reinterpret_cast<const float2*>(W + (size_t)n * 128);
#pragma unroll
        for (int p = 0; p < 64; ++p) {
            float2 v = wr[p];
            pack_hilo(v.x, v.y, hi[p], lo[p]);
        }
    } else {
        int i = (blockIdx.x - 4) * 256 + threadIdx.x;
        if (i < N_NODES) g_indeg[i] = 0;
    }
}

// ---------------- in-degree histogram (4 edges/thread, int4 loads) ------------
__global__ void k_hist(const int* __restrict__ dst) {
    int i = blockIdx.x * blockDim.x + threadIdx.x;
    if (i * 4 >= N_EDGES) return;
    int4 d = reinterpret_cast<const int4*>(dst)[i];
    atomicAdd(&g_indeg[d.x], 1);
    atomicAdd(&g_indeg[d.y], 1);
    atomicAdd(&g_indeg[d.z], 1);
    atomicAdd(&g_indeg[d.w], 1);
}

// ---------------- 3-phase full-chip scan --------------------------------------
__global__ __launch_bounds__(SCAN_BLK) void k_scanA() {
    __shared__ int ws[8];
    int t = threadIdx.x, lane = t & 31, wid = t >> 5;
    int i = blockIdx.x * SCAN_BLK + t;
    int v = (i < N_NODES) ? g_indeg[i] : 0;
    int s = v;
#pragma unroll
    for (int o = 16; o > 0; o >>= 1) s += __shfl_xor_sync(0xffffffffu, s, o);
    if (lane == 0) ws[wid] = s;
    __syncthreads();
    if (t < 8) {
        int x = ws[t];
#pragma unroll
        for (int o = 4; o > 0; o >>= 1) x += __shfl_xor_sync(0xffu, x, o);
        if (t == 0) g_bsum[blockIdx.x] = x;
    }
}

__global__ __launch_bounds__(256) void k_scanB() {
    __shared__ int ws[8];
    int t = threadIdx.x, lane = t & 31, wid = t >> 5;
    int v = (t < SCAN_NB) ? g_bsum[t] : 0;
    int x = v;
#pragma unroll
    for (int o = 1; o < 32; o <<= 1) {
        int y = __shfl_up_sync(0xffffffffu, x, o);
        if (lane >= o) x += y;
    }
    if (lane == 31) ws[wid] = x;
    __syncthreads();
    if (wid == 0 && lane < 8) {
        int s = ws[lane];
#pragma unroll
        for (int o = 1; o < 8; o <<= 1) {
            int y = __shfl_up_sync(0xffu, s, o);
            if (lane >= o) s += y;
        }
        ws[lane] = s;
    }
    __syncthreads();
    int incl = x + (wid ? ws[wid - 1] : 0);
    if (t < SCAN_NB) g_bbase[t] = incl - v;
    if (t == 255) g_off[N_NODES] = incl;
}

__global__ __launch_bounds__(SCAN_BLK) void k_scanC() {
    __shared__ int ws[8];
    int t = threadIdx.x, lane = t & 31, wid = t >> 5;
    int i = blockIdx.x * SCAN_BLK + t;
    int v = (i < N_NODES) ? g_indeg[i] : 0;
    int x = v;
#pragma unroll
    for (int o = 1; o < 32; o <<= 1) {
        int y = __shfl_up_sync(0xffffffffu, x, o);
        if (lane >= o) x += y;
    }
    if (lane == 31) ws[wid] = x;
    __syncthreads();
    if (wid == 0 && lane < 8) {
        int s = ws[lane];
#pragma unroll
        for (int o = 1; o < 8; o <<= 1) {
            int y = __shfl_up_sync(0xffu, s, o);
            if (lane >= o) s += y;
        }
        ws[lane] = s;
    }
    __syncthreads();
    if (i < N_NODES) {
        int off = g_bbase[blockIdx.x] + (wid ? ws[wid - 1] : 0) + (x - v);
        g_off[i] = off;
        g_cur[i] = off;
        g_deg[i] = rsqrtf((float)v + 1.f);
    }
}

// ---------------- CSR bucket fill (packed, 2 edges/thread) --------------------
__global__ void k_fill(const int* __restrict__ src, const int* __restrict__ dst) {
    int i = blockIdx.x * blockDim.x + threadIdx.x;
    int e = i * 2;
    if (e >= N_EDGES) return;
    int2 s2 = reinterpret_cast<const int2*>(src)[i];
    int2 d2 = reinterpret_cast<const int2*>(dst)[i];
    int slot0 = atomicAdd(&g_cur[d2.x], 1);
    int slot1 = atomicAdd(&g_cur[d2.y], 1);
    g_epack[slot0] = make_int2(s2.x, __float_as_int(g_deg[s2.x] * g_deg[d2.x]));
    g_epack[slot1] = make_int2(s2.y, __float_as_int(g_deg[s2.y] * g_deg[d2.y]));
}

// ---------------- tensor-core GEMM: C[M,128] = A[M,128] @ W^T (+bias) --------
#define GSTR 36
#define GEMM_SMEM (4 * 128 * GSTR * 4)    // 73728 B

__global__ __launch_bounds__(256) void k_gemmmma(
    const float* A_ext, int mat, const float* __restrict__ bias, int M, int mode)
{
    extern __shared__ uint32_t sm[];
    uint32_t* AsHi = sm;
    uint32_t* AsLo = sm + 128 * GSTR;
    uint32_t* WsHi = sm + 2 * 128 * GSTR;
    uint32_t* WsLo = sm + 3 * 128 * GSTR;

    const float* A = (mode == 0) ? A_ext : g_h;
    float* C = (mode == 0) ? g_h : g_hw;

    int t = threadIdx.x;
    int lane = t & 31, w = t >> 5;
    int wm = w >> 1;
    int wn = w & 1;
    int lr = lane >> 2, lq = lane & 3;
    int row0 = blockIdx.x * 128;

    int cr = t >> 1;
    int ch = t & 1;

    float acc[2][8][4];
#pragma unroll
    for (int i = 0; i < 2; ++i)
#pragma unroll
        for (int j = 0; j < 8; ++j)
#pragma unroll
            for (int q = 0; q < 4; ++q) acc[i][j][q] = 0.f;

    const uint32_t* gwH = g_wbf + (size_t)mat * 16384;

#pragma unroll 1
    for (int c = 0; c < 2; ++c) {
        {
            int gr = row0 + cr;
            const float4* arow = (gr < M)
                ? reinterpret_cast<const float4*>(A + (size_t)gr * 128 + c * 64 + ch * 32)
                : (const float4*)0;
            uint4* dh = reinterpret_cast<uint4*>(AsHi + cr * GSTR + ch * 16);
            uint4* dl = reinterpret_cast<uint4*>(AsLo + cr * GSTR + ch * 16);
#pragma unroll
            for (int i = 0; i < 4; ++i) {
                float4 v0 = arow ? arow[2 * i] : make_float4(0.f, 0.f, 0.f, 0.f);
                float4 v1 = arow ? arow[2 * i + 1] : make_float4(0.f, 0.f, 0.f, 0.f);
                uint32_t hp0, lp0, hp1, lp1, hp2, lp2, hp3, lp3;
                pack_hilo(v0.x, v0.y, hp0, lp0);
                pack_hilo(v0.z, v0.w, hp1, lp1);
                pack_hilo(v1.x, v1.y, hp2, lp2);
                pack_hilo(v1.z, v1.w, hp3, lp3);
                dh[i] = make_uint4(hp0, hp1, hp2, hp3);
                dl[i] = make_uint4(lp0, lp1, lp2, lp3);
            }
            const uint4* sH = reinterpret_cast<const uint4*>(
                gwH + cr * 64 + c * 32 + ch * 16);
            const uint4* sL = reinterpret_cast<const uint4*>(
                gwH + 8192 + cr * 64 + c * 32 + ch * 16);
            uint4* wh = reinterpret_cast<uint4*>(WsHi + cr * GSTR + ch * 16);
            uint4* wl = reinterpret_cast<uint4*>(WsLo + cr * GSTR + ch * 16);
#pragma unroll
            for (int i = 0; i < 4; ++i) { wh[i] = sH[i]; wl[i] = sL[i]; }
        }
        __syncthreads();

#pragma unroll
        for (int s = 0; s < 4; ++s) {
            int w0 = s * 8 + lq;
            uint32_t ah[2][4], al[2][4];
#pragma unroll
            for (int tm = 0; tm < 2; ++tm) {
                int ra = (wm * 32 + tm * 16 + lr) * GSTR + w0;
                ah[tm][0] = AsHi[ra];
                ah[tm][1] = AsHi[ra + 8 * GSTR];
                ah[tm][2] = AsHi[ra + 4];
                ah[tm][3] = AsHi[ra + 8 * GSTR + 4];
                al[tm][0] = AsLo[ra];
                al[tm][1] = AsLo[ra + 8 * GSTR];
                al[tm][2] = AsLo[ra + 4];
                al[tm][3] = AsLo[ra + 8 * GSTR + 4];
            }
#pragma unroll
            for (int j = 0; j < 8; ++j) {
                int rb = (wn * 64 + j * 8 + lr) * GSTR + w0;
                uint32_t bh0 = WsHi[rb], bh1 = WsHi[rb + 4];
                uint32_t bl0 = WsLo[rb], bl1 = WsLo[rb + 4];
#pragma unroll
                for (int tm = 0; tm < 2; ++tm) {
                    MMA_BF16(acc[tm][j], ah[tm], bh0, bh1);
                    MMA_BF16(acc[tm][j], ah[tm], bl0, bl1);
                    MMA_BF16(acc[tm][j], al[tm], bh0, bh1);
                }
            }
        }
        __syncthreads();
    }

#pragma unroll
    for (int tm = 0; tm < 2; ++tm) {
        int row = row0 + wm * 32 + tm * 16 + lr;
#pragma unroll
        for (int j = 0; j < 8; ++j) {
            int col = wn * 64 + j * 8 + lq * 2;
            float bx = 0.f, by = 0.f;
            if (bias) {
                float2 bv = *reinterpret_cast<const float2*>(bias + col);
                bx = bv.x; by = bv.y;
            }
            if (row < M) {
                float2 v = make_float2(acc[tm][j][0] + bx, acc[tm][j][1] + by);
                *reinterpret_cast<float2*>(C + (size_t)row * 128 + col) = v;
            }
            if (row + 8 < M) {
                float2 v = make_float2(acc[tm][j][2] + bx, acc[tm][j][3] + by);
                *reinterpret_cast<float2*>(C + (size_t)(row + 8) * 128 + col) = v;
            }
        }
    }
}

// ---------------- fused gather + self-loop + LN + ReLU + residual ------------
// warp per dst node, 8 edges in flight (round-10 proven form — frozen).
#define EDGE4(E)                                                                \
    {                                                                           \
        int2 p0 = g_epack[E], p1 = g_epack[(E) + 1];                            \
        int2 p2 = g_epack[(E) + 2], p3 = g_epack[(E) + 3];                      \
        float4 v0 = reinterpret_cast<const float4*>(g_hw + (size_t)p0.x * HID)[lane]; \
        float4 v1 = reinterpret_cast<const float4*>(g_hw + (size_t)p1.x * HID)[lane]; \
        float4 v2 = reinterpret_cast<const float4*>(g_hw + (size_t)p2.x * HID)[lane]; \
        float4 v3 = reinterpret_cast<const float4*>(g_hw + (size_t)p3.x * HID)[lane]; \
        float w0 = __int_as_float(p0.y), w1 = __int_as_float(p1.y);             \
        float w2 = __int_as_float(p2.y), w3 = __int_as_float(p3.y);             \
        acc.x += w0 * v0.x + w1 * v1.x + w2 * v2.x + w3 * v3.x;                 \
        acc.y += w0 * v0.y + w1 * v1.y + w2 * v2.y + w3 * v3.y;                 \
        acc.z += w0 * v0.z + w1 * v1.z + w2 * v2.z + w3 * v3.z;                 \
        acc.w += w0 * v0.w + w1 * v1.w + w2 * v2.w + w3 * v3.w;                 \
    }

__global__ __launch_bounds__(256) void k_gatherln(
    const float* __restrict__ bc,
    const float* __restrict__ gamma, const float* __restrict__ beta)
{
    int node = (blockIdx.x * blockDim.x + threadIdx.x) >> 5;
    int lane = threadIdx.x & 31;
    if (node >= N_NODES) return;

    int e0 = g_off[node], e1 = g_off[node + 1];
    float dv = g_deg[node];
    float sn = dv * dv;

    float4 hv  = reinterpret_cast<const float4*>(g_hw + (size_t)node * HID)[lane];
    float4 bcv = reinterpret_cast<const float4*>(bc)[lane];
    float4 acc = make_float4(hv.x * sn + bcv.x, hv.y * sn + bcv.y,
                             hv.z * sn + bcv.z, hv.w * sn + bcv.w);

    int e = e0;
#pragma unroll 1
    for (; e + 8 <= e1; e += 8) {
        EDGE4(e)
        EDGE4(e + 4)
    }
    if (e + 4 <= e1) { EDGE4(e) e += 4; }
#pragma unroll 1
    for (; e < e1; ++e) {
        int2 p = g_epack[e];
        float w = __int_as_float(p.y);
        float4 v = reinterpret_cast<const float4*>(g_hw + (size_t)p.x * HID)[lane];
        acc.x += w * v.x; acc.y += w * v.y;
        acc.z += w * v.z; acc.w += w * v.w;
    }

    float s = acc.x + acc.y + acc.z + acc.w;
#pragma unroll
    for (int o = 16; o > 0; o >>= 1) s += __shfl_xor_sync(0xffffffffu, s, o);
    float mu = s * (1.f / 128.f);
    float dx = acc.x - mu, dy = acc.y - mu, dz = acc.z - mu, dw = acc.w - mu;
    float q = dx * dx + dy * dy + dz * dz + dw * dw;
#pragma unroll
    for (int o = 16; o > 0; o >>= 1) q += __shfl_xor_sync(0xffffffffu, q, o);
    float rs = rsqrtf(q * (1.f / 128.f) + LN_EPS);

    float4 gm = reinterpret_cast<const float4*>(gamma)[lane];
    float4 bt = reinterpret_cast<const float4*>(beta)[lane];
    float4 r  = reinterpret_cast<const float4*>(g_h + (size_t)node * HID)[lane];
    float4 o;
    o.x = fmaxf(dx * rs * gm.x + bt.x, 0.f) + r.x;
    o.y = fmaxf(dy * rs * gm.y + bt.y, 0.f) + r.y;
    o.z = fmaxf(dz * rs * gm.z + bt.z, 0.f) + r.z;
    o.w = fmaxf(dw * rs * gm.w + bt.w, 0.f) + r.w;
    reinterpret_cast<float4*>(g_h + (size_t)node * HID)[lane] = o;
}

// ---------------- fused pool + MLP (block per graph, atomic-free) ------------
__global__ __launch_bounds__(128) void k_poolmlp(
    const int* __restrict__ batch,
    const float* __restrict__ W1, const float* __restrict__ b1,
    const float* __restrict__ W2, const float* __restrict__ b2,
    float* __restrict__ out)
{
    __shared__ float sp[128];
    __shared__ float part[2];
    int g = blockIdx.x, t = threadIdx.x;

    int lo = 0, hi = N_NODES;
    while (lo < hi) { int m = (lo + hi) >> 1; if (batch[m] < g) lo = m + 1; else hi = m; }
    int start = lo;
    hi = N_NODES;
    while (lo < hi) { int m = (lo + hi) >> 1; if (batch[m] < g + 1) lo = m + 1; else hi = m; }
    int end = lo;

    float acc = 0.f;
    for (int r = start; r < end; ++r) acc += g_h[(size_t)r * HID + t];
    float inv = 1.f / fmaxf((float)(end - start), 1.f);
    sp[t] = acc * inv;
    __syncthreads();

    if (t < 64) {
        float a = b1[t];
#pragma unroll 8
        for (int k = 0; k < 128; ++k) a += sp[k] * W1[t * 128 + k];
        a = fmaxf(a, 0.f);
        float v = a * W2[t];
#pragma unroll
        for (int o = 16; o > 0; o >>= 1) v += __shfl_xor_sync(0xffffffffu, v, o);
        if ((t & 31) == 0) part[t >> 5] = v;
    }
    __syncthreads();
    if (t == 0) out[g] = part[0] + part[1] + b2[0];
}

// ---------------- launch -----------------------------------------------------
extern "C" void kernel_launch(void* const* d_in, const int* in_sizes, int n_in,
                              void* d_out, int out_size) {
    const float* x     = (const float*)d_in[0];
    const int*   ei    = (const int*)  d_in[1];
    const int*   batch = (const int*)  d_in[2];
    const float* W_in  = (const float*)d_in[3];
    const float* b_in  = (const float*)d_in[4];
    const float* Wc    = (const float*)d_in[5];
    const float* bc    = (const float*)d_in[6];
    const float* gamma = (const float*)d_in[7];
    const float* beta  = (const float*)d_in[8];
    const float* W1    = (const float*)d_in[9];
    const float* b1    = (const float*)d_in[10];
    const float* W2    = (const float*)d_in[11];
    const float* b2    = (const float*)d_in[12];
    float* out = (float*)d_out;

    const int* src = ei;
    const int* dst = ei + N_EDGES;

    cudaFuncSetAttribute(k_gemmmma, cudaFuncAttributeMaxDynamicSharedMemorySize,
                         GEMM_SMEM);

    k_initwconv<<<4 + (N_NODES + 255) / 256, 256>>>(W_in, Wc);
    k_hist<<<(N_EDGES / 4 + 255) / 256, 256>>>(dst);
    k_scanA<<<SCAN_NB, SCAN_BLK>>>();
    k_scanB<<<1, 256>>>();
    k_scanC<<<SCAN_NB, SCAN_BLK>>>();
    k_fill<<<(N_EDGES / 2 + 255) / 256, 256>>>(src, dst);

    int gemm_blocks = (N_NODES + 127) / 128;   // 391
    k_gemmmma<<<gemm_blocks, 256, GEMM_SMEM>>>(x, 0, b_in, N_NODES, 0);

    int gl_blocks = (N_NODES * 32 + 255) / 256;
    for (int l = 0; l < N_LAYERS; ++l) {
        k_gemmmma<<<gemm_blocks, 256, GEMM_SMEM>>>((const float*)0, l + 1,
                                                   (const float*)0, N_NODES, 1);
        k_gatherln<<<gl_blocks, 256>>>(bc + l * HID, gamma + l * HID, beta + l * HID);
    }

    k_poolmlp<<<NUM_GRAPHS, 128>>>(batch, W1, b1, W2, b2, out);
}

// round 15
// speedup vs baseline: 1.4690x; 1.0024x over previous
#include <cuda_runtime.h>
#include <cuda_bf16.h>
#include <cstdint>

#define N_NODES 50000
#define N_EDGES 800000
#define HID 128
#define NUM_GRAPHS 500
#define N_LAYERS 3
#define LN_EPS 1e-5f

#define SCAN_BLK 256
#define SCAN_NB  ((N_NODES + SCAN_BLK - 1) / SCAN_BLK)   // 196

// ---------------- scratch (device globals) ----------------------------------
__device__ float g_deg[N_NODES];                      // dinv
__device__ int   g_indeg[N_NODES];
__device__ int   g_off[N_NODES + 1];
__device__ int   g_cur[N_NODES];
__device__ int   g_bsum[SCAN_NB];
__device__ int   g_bbase[SCAN_NB];
__device__ int2  g_epack[N_EDGES];                    // {src, bits(weight)}
__device__ float g_h[(size_t)N_NODES * HID];
__device__ float g_hw[(size_t)N_NODES * HID];
// per mat: hi 8192 u32 (n*64 + kpair), lo 8192 u32
__device__ uint32_t g_wbf[4 * 16384];

// ---------------- bf16 hi/lo pack helper -------------------------------------
__device__ __forceinline__ void pack_hilo(float x0, float x1,
                                          uint32_t& hp, uint32_t& lp) {
    unsigned short h0 = __bfloat16_as_ushort(__float2bfloat16(x0));
    unsigned short h1 = __bfloat16_as_ushort(__float2bfloat16(x1));
    float r0 = x0 - __uint_as_float((uint32_t)h0 << 16);
    float r1 = x1 - __uint_as_float((uint32_t)h1 << 16);
    unsigned short l0 = __bfloat16_as_ushort(__float2bfloat16(r0));
    unsigned short l1 = __bfloat16_as_ushort(__float2bfloat16(r1));
    hp = (uint32_t)h0 | ((uint32_t)h1 << 16);
    lp = (uint32_t)l0 | ((uint32_t)l1 << 16);
}

#define MMA_BF16(d, a, bv0, bv1)                                                \
    asm volatile("mma.sync.aligned.m16n8k16.row.col.f32.bf16.bf16.f32 "         \
        "{%0,%1,%2,%3}, {%4,%5,%6,%7}, {%8,%9}, {%0,%1,%2,%3};"                 \
        : "+f"((d)[0]), "+f"((d)[1]), "+f"((d)[2]), "+f"((d)[3])                \
        : "r"((a)[0]), "r"((a)[1]), "r"((a)[2]), "r"((a)[3]),                   \
          "r"(bv0), "r"(bv1));

// ---------------- merged init (indeg zero) + weight convert -------------------
__global__ __launch_bounds__(256) void k_initwconv(const float* __restrict__ W_in,
                                                   const float* __restrict__ Wc) {
    if (blockIdx.x < 4) {
        int mat = blockIdx.x;             // 0 = W_in, 1..3 = Wc[l]
        int n = threadIdx.x;
        if (n >= 128) return;
        const float* W = (mat == 0) ? W_in : Wc + (size_t)(mat - 1) * 16384;
        uint32_t* hi = g_wbf + (size_t)mat * 16384 + n * 64;
        uint32_t* lo = hi + 8192;
        const float2* wr = reinterpret_cast<const float2*>(W + (size_t)n * 128);
#pragma unroll
        for (int p = 0; p < 64; ++p) {
            float2 v = wr[p];
            pack_hilo(v.x, v.y, hi[p], lo[p]);
        }
    } else {
        int i = (blockIdx.x - 4) * 256 + threadIdx.x;
        if (i < N_NODES) g_indeg[i] = 0;
    }
}

// ---------------- in-degree histogram (4 edges/thread, int4 loads) ------------
__global__ void k_hist(const int* __restrict__ dst) {
    int i = blockIdx.x * blockDim.x + threadIdx.x;
    if (i * 4 >= N_EDGES) return;
    int4 d = __ldg(reinterpret_cast<const int4*>(dst) + i);
    atomicAdd(&g_indeg[d.x], 1);
    atomicAdd(&g_indeg[d.y], 1);
    atomicAdd(&g_indeg[d.z], 1);
    atomicAdd(&g_indeg[d.w], 1);
}

// ---------------- 3-phase full-chip scan --------------------------------------
__global__ __launch_bounds__(SCAN_BLK) void k_scanA() {
    __shared__ int ws[8];
    int t = threadIdx.x, lane = t & 31, wid = t >> 5;
    int i = blockIdx.x * SCAN_BLK + t;
    int v = (i < N_NODES) ? g_indeg[i] : 0;
    int s = v;
#pragma unroll
    for (int o = 16; o > 0; o >>= 1) s += __shfl_xor_sync(0xffffffffu, s, o);
    if (lane == 0) ws[wid] = s;
    __syncthreads();
    if (t < 8) {
        int x = ws[t];
#pragma unroll
        for (int o = 4; o > 0; o >>= 1) x += __shfl_xor_sync(0xffu, x, o);
        if (t == 0) g_bsum[blockIdx.x] = x;
    }
}

__global__ __launch_bounds__(256) void k_scanB() {
    __shared__ int ws[8];
    int t = threadIdx.x, lane = t & 31, wid = t >> 5;
    int v = (t < SCAN_NB) ? g_bsum[t] : 0;
    int x = v;
#pragma unroll
    for (int o = 1; o < 32; o <<= 1) {
        int y = __shfl_up_sync(0xffffffffu, x, o);
        if (lane >= o) x += y;
    }
    if (lane == 31) ws[wid] = x;
    __syncthreads();
    if (wid == 0 && lane < 8) {
        int s = ws[lane];
#pragma unroll
        for (int o = 1; o < 8; o <<= 1) {
            int y = __shfl_up_sync(0xffu, s, o);
            if (lane >= o) s += y;
        }
        ws[lane] = s;
    }
    __syncthreads();
    int incl = x + (wid ? ws[wid - 1] : 0);
    if (t < SCAN_NB) g_bbase[t] = incl - v;
    if (t == 255) g_off[N_NODES] = incl;
}

__global__ __launch_bounds__(SCAN_BLK) void k_scanC() {
    __shared__ int ws[8];
    int t = threadIdx.x, lane = t & 31, wid = t >> 5;
    int i = blockIdx.x * SCAN_BLK + t;
    int v = (i < N_NODES) ? g_indeg[i] : 0;
    int x = v;
#pragma unroll
    for (int o = 1; o < 32; o <<= 1) {
        int y = __shfl_up_sync(0xffffffffu, x, o);
        if (lane >= o) x += y;
    }
    if (lane == 31) ws[wid] = x;
    __syncthreads();
    if (wid == 0 && lane < 8) {
        int s = ws[lane];
#pragma unroll
        for (int o = 1; o < 8; o <<= 1) {
            int y = __shfl_up_sync(0xffu, s, o);
            if (lane >= o) s += y;
        }
        ws[lane] = s;
    }
    __syncthreads();
    if (i < N_NODES) {
        int off = g_bbase[blockIdx.x] + (wid ? ws[wid - 1] : 0) + (x - v);
        g_off[i] = off;
        g_cur[i] = off;
        g_deg[i] = rsqrtf((float)v + 1.f);
    }
}

// ---------------- CSR bucket fill (packed, 2 edges/thread) --------------------
__global__ void k_fill(const int* __restrict__ src, const int* __restrict__ dst) {
    int i = blockIdx.x * blockDim.x + threadIdx.x;
    int e = i * 2;
    if (e >= N_EDGES) return;
    int2 s2 = __ldg(reinterpret_cast<const int2*>(src) + i);
    int2 d2 = __ldg(reinterpret_cast<const int2*>(dst) + i);
    int slot0 = atomicAdd(&g_cur[d2.x], 1);
    int slot1 = atomicAdd(&g_cur[d2.y], 1);
    g_epack[slot0] = make_int2(s2.x, __float_as_int(g_deg[s2.x] * g_deg[d2.x]));
    g_epack[slot1] = make_int2(s2.y, __float_as_int(g_deg[s2.y] * g_deg[d2.y]));
}

// ---------------- tensor-core GEMM: C[M,128] = A[M,128] @ W^T (+bias) --------
#define GSTR 36
#define GEMM_SMEM (4 * 128 * GSTR * 4)    // 73728 B

__global__ __launch_bounds__(256) void k_gemmmma(
    const float* A_ext, int mat, const float* __restrict__ bias, int M, int mode)
{
    extern __shared__ uint32_t sm[];
    uint32_t* AsHi = sm;
    uint32_t* AsLo = sm + 128 * GSTR;
    uint32_t* WsHi = sm + 2 * 128 * GSTR;
    uint32_t* WsLo = sm + 3 * 128 * GSTR;

    const float* A = (mode == 0) ? A_ext : g_h;
    float* C = (mode == 0) ? g_h : g_hw;

    int t = threadIdx.x;
    int lane = t & 31, w = t >> 5;
    int wm = w >> 1;
    int wn = w & 1;
    int lr = lane >> 2, lq = lane & 3;
    int row0 = blockIdx.x * 128;

    int cr = t >> 1;
    int ch = t & 1;

    float acc[2][8][4];
#pragma unroll
    for (int i = 0; i < 2; ++i)
#pragma unroll
        for (int j = 0; j < 8; ++j)
#pragma unroll
            for (int q = 0; q < 4; ++q) acc[i][j][q] = 0.f;

    const uint32_t* gwH = g_wbf + (size_t)mat * 16384;

#pragma unroll 1
    for (int c = 0; c < 2; ++c) {
        {
            int gr = row0 + cr;
            const float4* arow = (gr < M)
                ? reinterpret_cast<const float4*>(A + (size_t)gr * 128 + c * 64 + ch * 32)
                : (const float4*)0;
            uint4* dh = reinterpret_cast<uint4*>(AsHi + cr * GSTR + ch * 16);
            uint4* dl = reinterpret_cast<uint4*>(AsLo + cr * GSTR + ch * 16);
#pragma unroll
            for (int i = 0; i < 4; ++i) {
                float4 v0 = arow ? __ldg(arow + 2 * i) : make_float4(0.f, 0.f, 0.f, 0.f);
                float4 v1 = arow ? __ldg(arow + 2 * i + 1) : make_float4(0.f, 0.f, 0.f, 0.f);
                uint32_t hp0, lp0, hp1, lp1, hp2, lp2, hp3, lp3;
                pack_hilo(v0.x, v0.y, hp0, lp0);
                pack_hilo(v0.z, v0.w, hp1, lp1);
                pack_hilo(v1.x, v1.y, hp2, lp2);
                pack_hilo(v1.z, v1.w, hp3, lp3);
                dh[i] = make_uint4(hp0, hp1, hp2, hp3);
                dl[i] = make_uint4(lp0, lp1, lp2, lp3);
            }
            const uint4* sH = reinterpret_cast<const uint4*>(
                gwH + cr * 64 + c * 32 + ch * 16);
            const uint4* sL = reinterpret_cast<const uint4*>(
                gwH + 8192 + cr * 64 + c * 32 + ch * 16);
            uint4* wh = reinterpret_cast<uint4*>(WsHi + cr * GSTR + ch * 16);
            uint4* wl = reinterpret_cast<uint4*>(WsLo + cr * GSTR + ch * 16);
#pragma unroll
            for (int i = 0; i < 4; ++i) { wh[i] = __ldg(sH + i); wl[i] = __ldg(sL + i); }
        }
        __syncthreads();

#pragma unroll
        for (int s = 0; s < 4; ++s) {
            int w0 = s * 8 + lq;
            uint32_t ah[2][4], al[2][4];
#pragma unroll
            for (int tm = 0; tm < 2; ++tm) {
                int ra = (wm * 32 + tm * 16 + lr) * GSTR + w0;
                ah[tm][0] = AsHi[ra];
                ah[tm][1] = AsHi[ra + 8 * GSTR];
                ah[tm][2] = AsHi[ra + 4];
                ah[tm][3] = AsHi[ra + 8 * GSTR + 4];
                al[tm][0] = AsLo[ra];
                al[tm][1] = AsLo[ra + 8 * GSTR];
                al[tm][2] = AsLo[ra + 4];
                al[tm][3] = AsLo[ra + 8 * GSTR + 4];
            }
#pragma unroll
            for (int j = 0; j < 8; ++j) {
                int rb = (wn * 64 + j * 8 + lr) * GSTR + w0;
                uint32_t bh0 = WsHi[rb], bh1 = WsHi[rb + 4];
                uint32_t bl0 = WsLo[rb], bl1 = WsLo[rb + 4];
#pragma unroll
                for (int tm = 0; tm < 2; ++tm) {
                    MMA_BF16(acc[tm][j], ah[tm], bh0, bh1);
                    MMA_BF16(acc[tm][j], ah[tm], bl0, bl1);
                    MMA_BF16(acc[tm][j], al[tm], bh0, bh1);
                }
            }
        }
        __syncthreads();
    }

#pragma unroll
    for (int tm = 0; tm < 2; ++tm) {
        int row = row0 + wm * 32 + tm * 16 + lr;
#pragma unroll
        for (int j = 0; j < 8; ++j) {
            int col = wn * 64 + j * 8 + lq * 2;
            float bx = 0.f, by = 0.f;
            if (bias) {
                float2 bv = *reinterpret_cast<const float2*>(bias + col);
                bx = bv.x; by = bv.y;
            }
            if (row < M) {
                float2 v = make_float2(acc[tm][j][0] + bx, acc[tm][j][1] + by);
                *reinterpret_cast<float2*>(C + (size_t)row * 128 + col) = v;
            }
            if (row + 8 < M) {
                float2 v = make_float2(acc[tm][j][2] + bx, acc[tm][j][3] + by);
                *reinterpret_cast<float2*>(C + (size_t)(row + 8) * 128 + col) = v;
            }
        }
    }
}

// ---------------- fused gather + self-loop + LN + ReLU + residual ------------
// warp per dst node, 8 edges in flight (round-10 proven form); read-only loads
// routed through __ldg (LDG.NC) for L1 allocation on the streaming epack reads.
#define EDGE4(E)                                                                \
    {                                                                           \
        int2 p0 = __ldg(g_epack + (E));     int2 p1 = __ldg(g_epack + (E) + 1); \
        int2 p2 = __ldg(g_epack + (E) + 2); int2 p3 = __ldg(g_epack + (E) + 3); \
        float4 v0 = __ldg(reinterpret_cast<const float4*>(g_hw + (size_t)p0.x * HID) + lane); \
        float4 v1 = __ldg(reinterpret_cast<const float4*>(g_hw + (size_t)p1.x * HID) + lane); \
        float4 v2 = __ldg(reinterpret_cast<const float4*>(g_hw + (size_t)p2.x * HID) + lane); \
        float4 v3 = __ldg(reinterpret_cast<const float4*>(g_hw + (size_t)p3.x * HID) + lane); \
        float w0 = __int_as_float(p0.y), w1 = __int_as_float(p1.y);             \
        float w2 = __int_as_float(p2.y), w3 = __int_as_float(p3.y);             \
        acc.x += w0 * v0.x + w1 * v1.x + w2 * v2.x + w3 * v3.x;                 \
        acc.y += w0 * v0.y + w1 * v1.y + w2 * v2.y + w3 * v3.y;                 \
        acc.z += w0 * v0.z + w1 * v1.z + w2 * v2.z + w3 * v3.z;                 \
        acc.w += w0 * v0.w + w1 * v1.w + w2 * v2.w + w3 * v3.w;                 \
    }

__global__ __launch_bounds__(256) void k_gatherln(
    const float* __restrict__ bc,
    const float* __restrict__ gamma, const float* __restrict__ beta)
{
    int node = (blockIdx.x * blockDim.x + threadIdx.x) >> 5;
    int lane = threadIdx.x & 31;
    if (node >= N_NODES) return;

    int e0 = __ldg(g_off + node), e1 = __ldg(g_off + node + 1);
    float dv = __ldg(g_deg + node);
    float sn = dv * dv;

    float4 hv  = __ldg(reinterpret_cast<const float4*>(g_hw + (size_t)node * HID) + lane);
    float4 bcv = __ldg(reinterpret_cast<const float4*>(bc) + lane);
    float4 acc = make_float4(hv.x * sn + bcv.x, hv.y * sn + bcv.y,
                             hv.z * sn + bcv.z, hv.w * sn + bcv.w);

    int e = e0;
#pragma unroll 1
    for (; e + 8 <= e1; e += 8) {
        EDGE4(e)
        EDGE4(e + 4)
    }
    if (e + 4 <= e1) { EDGE4(e) e += 4; }
#pragma unroll 1
    for (; e < e1; ++e) {
        int2 p = __ldg(g_epack + e);
        float w = __int_as_float(p.y);
        float4 v = __ldg(reinterpret_cast<const float4*>(g_hw + (size_t)p.x * HID) + lane);
        acc.x += w * v.x; acc.y += w * v.y;
        acc.z += w * v.z; acc.w += w * v.w;
    }

    float s = acc.x + acc.y + acc.z + acc.w;
#pragma unroll
    for (int o = 16; o > 0; o >>= 1) s += __shfl_xor_sync(0xffffffffu, s, o);
    float mu = s * (1.f / 128.f);
    float dx = acc.x - mu, dy = acc.y - mu, dz = acc.z - mu, dw = acc.w - mu;
    float q = dx * dx + dy * dy + dz * dz + dw * dw;
#pragma unroll
    for (int o = 16; o > 0; o >>= 1) q += __shfl_xor_sync(0xffffffffu, q, o);
    float rs = rsqrtf(q * (1.f / 128.f) + LN_EPS);

    float4 gm = __ldg(reinterpret_cast<const float4*>(gamma) + lane);
    float4 bt = __ldg(reinterpret_cast<const float4*>(beta) + lane);
    float4 r  = reinterpret_cast<const float4*>(g_h + (size_t)node * HID)[lane];
    float4 o;
    o.x = fmaxf(dx * rs * gm.x + bt.x, 0.f) + r.x;
    o.y = fmaxf(dy * rs * gm.y + bt.y, 0.f) + r.y;
    o.z = fmaxf(dz * rs * gm.z + bt.z, 0.f) + r.z;
    o.w = fmaxf(dw * rs * gm.w + bt.w, 0.f) + r.w;
    reinterpret_cast<float4*>(g_h + (size_t)node * HID)[lane] = o;
}

// ---------------- fused pool + MLP (block per graph, atomic-free) ------------
__global__ __launch_bounds__(128) void k_poolmlp(
    const int* __restrict__ batch,
    const float* __restrict__ W1, const float* __restrict__ b1,
    const float* __restrict__ W2, const float* __restrict__ b2,
    float* __restrict__ out)
{
    __shared__ float sp[128];
    __shared__ float part[2];
    int g = blockIdx.x, t = threadIdx.x;

    int lo = 0, hi = N_NODES;
    while (lo < hi) { int m = (lo + hi) >> 1; if (batch[m] < g) lo = m + 1; else hi = m; }
    int start = lo;
    hi = N_NODES;
    while (lo < hi) { int m = (lo + hi) >> 1; if (batch[m] < g + 1) lo = m + 1; else hi = m; }
    int end = lo;

    float acc = 0.f;
    for (int r = start; r < end; ++r) acc += g_h[(size_t)r * HID + t];
    float inv = 1.f / fmaxf((float)(end - start), 1.f);
    sp[t] = acc * inv;
    __syncthreads();

    if (t < 64) {
        float a = b1[t];
#pragma unroll 8
        for (int k = 0; k < 128; ++k) a += sp[k] * W1[t * 128 + k];
        a = fmaxf(a, 0.f);
        float v = a * W2[t];
#pragma unroll
        for (int o = 16; o > 0; o >>= 1) v += __shfl_xor_sync(0xffffffffu, v, o);
        if ((t & 31) == 0) part[t >> 5] = v;
    }
    __syncthreads();
    if (t == 0) out[g] = part[0] + part[1] + b2[0];
}

// ---------------- launch -----------------------------------------------------
extern "C" void kernel_launch(void* const* d_in, const int* in_sizes, int n_in,
                              void* d_out, int out_size) {
    const float* x     = (const float*)d_in[0];
    const int*   ei    = (const int*)  d_in[1];
    const int*   batch = (const int*)  d_in[2];
    const float* W_in  = (const float*)d_in[3];
    const float* b_in  = (const float*)d_in[4];
    const float* Wc    = (const float*)d_in[5];
    const float* bc    = (const float*)d_in[6];
    const float* gamma = (const float*)d_in[7];
    const float* beta  = (const float*)d_in[8];
    const float* W1    = (const float*)d_in[9];
    const float* b1    = (const float*)d_in[10];
    const float* W2    = (const float*)d_in[11];
    const float* b2    = (const float*)d_in[12];
    float* out = (float*)d_out;

    const int* src = ei;
    const int* dst = ei + N_EDGES;

    cudaFuncSetAttribute(k_gemmmma, cudaFuncAttributeMaxDynamicSharedMemorySize,
                         GEMM_SMEM);

    k_initwconv<<<4 + (N_NODES + 255) / 256, 256>>>(W_in, Wc);
    k_hist<<<(N_EDGES / 4 + 255) / 256, 256>>>(dst);
    k_scanA<<<SCAN_NB, SCAN_BLK>>>();
    k_scanB<<<1, 256>>>();
    k_scanC<<<SCAN_NB, SCAN_BLK>>>();
    k_fill<<<(N_EDGES / 2 + 255) / 256, 256>>>(src, dst);

    int gemm_blocks = (N_NODES + 127) / 128;   // 391
    k_gemmmma<<<gemm_blocks, 256, GEMM_SMEM>>>(x, 0, b_in, N_NODES, 0);

    int gl_blocks = (N_NODES * 32 + 255) / 256;
    for (int l = 0; l < N_LAYERS; ++l) {
        k_gemmmma<<<gemm_blocks, 256, GEMM_SMEM>>>((const float*)0, l + 1,
                                                   (const float*)0, N_NODES, 1);
        k_gatherln<<<gl_blocks, 256>>>(bc + l * HID, gamma + l * HID, beta + l * HID);
    }

    k_poolmlp<<<NUM_GRAPHS, 128>>>(batch, W1, b1, W2, b2, out);
}